// round 3
// baseline (speedup 1.0000x reference)
#include <cuda_runtime.h>

#define NN 50000
#define EE 800000
#define DM 128
#define RD 32
#define KIN 160
#define LN_EPS 1e-5f

// ---------------- scratch ----------------------------------------------------
__device__ float g_h[NN * DM];
__device__ float g_h2[NN * DM];
__device__ float g_inv[NN];
__device__ int   g_deg[NN];
__device__ int   g_off[NN + 1];
__device__ int   g_cur[NN];
__device__ int2  g_csr[EE];        // (src, rel) sorted by dst

// ---------------- small kernels ----------------------------------------------
__global__ void k_zero_int(int* __restrict__ p, int n) {
    int i = blockIdx.x * blockDim.x + threadIdx.x;
    if (i < n) p[i] = 0;
}

__global__ void k_deg(const int* __restrict__ dst) {
    int i = blockIdx.x * blockDim.x + threadIdx.x;
    if (i < EE) atomicAdd(&g_deg[dst[i]], 1);
}

// one block, 1024 threads: exclusive scan of g_deg -> g_off/g_cur, inv_deg
__global__ __launch_bounds__(1024) void k_scan() {
    __shared__ int warp_sums[32];
    const int CH = (NN + 1023) / 1024;   // 49
    int t = threadIdx.x, lane = t & 31, w = t >> 5;
    int base = t * CH;
    int s = 0;
    for (int i = 0; i < CH; i++) {
        int idx = base + i;
        if (idx < NN) s += g_deg[idx];
    }
    int v = s;
    #pragma unroll
    for (int o = 1; o < 32; o <<= 1) {
        int u = __shfl_up_sync(0xffffffffu, v, o);
        if (lane >= o) v += u;
    }
    if (lane == 31) warp_sums[w] = v;
    __syncthreads();
    if (w == 0) {
        int u = warp_sums[lane];
        #pragma unroll
        for (int o = 1; o < 32; o <<= 1) {
            int uu = __shfl_up_sync(0xffffffffu, u, o);
            if (lane >= o) u += uu;
        }
        warp_sums[lane] = u;
    }
    __syncthreads();
    int excl = v - s + (w > 0 ? warp_sums[w - 1] : 0);
    int run = excl;
    for (int i = 0; i < CH; i++) {
        int idx = base + i;
        if (idx < NN) {
            int d = g_deg[idx];
            g_off[idx] = run;
            g_cur[idx] = run;
            g_inv[idx] = d > 0 ? (1.f / (float)d) : 0.f;
            run += d;
        }
    }
    if (t == 0) g_off[NN] = EE;
}

__global__ void k_scatter(const int* __restrict__ src, const int* __restrict__ dst,
                          const int* __restrict__ erel) {
    int i = blockIdx.x * blockDim.x + threadIdx.x;
    if (i < EE) {
        int d = dst[i];
        int pos = atomicAdd(&g_cur[d], 1);
        g_csr[pos] = make_int2(src[i], erel[i]);
    }
}

extern __shared__ float smdyn[];

// ---------------- GEMM macros (4-row register blocking) -----------------------
#define FMA4(S0, S1, S2, S3, WV)                                   \
    a0.x += (S0) * (WV).x; a0.y += (S0) * (WV).y;                  \
    a0.z += (S0) * (WV).z; a0.w += (S0) * (WV).w;                  \
    a1.x += (S1) * (WV).x; a1.y += (S1) * (WV).y;                  \
    a1.z += (S1) * (WV).z; a1.w += (S1) * (WV).w;                  \
    a2.x += (S2) * (WV).x; a2.y += (S2) * (WV).y;                  \
    a2.z += (S2) * (WV).z; a2.w += (S2) * (WV).w;                  \
    a3.x += (S3) * (WV).x; a3.y += (S3) * (WV).y;                  \
    a3.z += (S3) * (WV).z; a3.w += (S3) * (WV).w;

#define SEG(Wb, OFF, LEN)                                              \
    _Pragma("unroll 8")                                                \
    for (int k = 0; k < (LEN); k += 4) {                               \
        float4 b0 = *(const float4*)(i0 + (OFF) + k);                  \
        float4 b1 = *(const float4*)(i1 + (OFF) + k);                  \
        float4 b2 = *(const float4*)(i2 + (OFF) + k);                  \
        float4 b3 = *(const float4*)(i3 + (OFF) + k);                  \
        { float4 wv = *(const float4*)((Wb) + (k + 0) * DM + c);       \
          FMA4(b0.x, b1.x, b2.x, b3.x, wv) }                           \
        { float4 wv = *(const float4*)((Wb) + (k + 1) * DM + c);       \
          FMA4(b0.y, b1.y, b2.y, b3.y, wv) }                           \
        { float4 wv = *(const float4*)((Wb) + (k + 2) * DM + c);       \
          FMA4(b0.z, b1.z, b2.z, b3.z, wv) }                           \
        { float4 wv = *(const float4*)((Wb) + (k + 3) * DM + c);       \
          FMA4(b0.w, b1.w, b2.w, b3.w, wv) }                           \
    }

// ---------------- input projection --------------------------------------------
__global__ __launch_bounds__(256) void k_input(
    const float* __restrict__ x, const int* __restrict__ label,
    const float* __restrict__ lemb, const float* __restrict__ W,
    const float* __restrict__ b, float* __restrict__ hout)
{
    float* Ws  = smdyn;
    float* bs  = Ws + KIN * DM;
    float* ins = bs + DM;
    int tid = threadIdx.x;

    for (int i = tid; i < (KIN * DM) / 4; i += 256)
        ((float4*)Ws)[i] = ((const float4*)W)[i];
    for (int i = tid; i < DM; i += 256) bs[i] = b[i];
    __syncthreads();

    int w = tid >> 5, lane = tid & 31;
    int c = lane * 4;
    const int ntiles = NN / 4;

    for (int tile = blockIdx.x * 8 + w; tile < ntiles; tile += gridDim.x * 8) {
        int v0 = tile * 4;
        float* in = ins + w * (4 * KIN);
        #pragma unroll
        for (int r = 0; r < 4; r++) {
            int v = v0 + r;
            float* inr = in + r * KIN;
            ((float4*)inr)[lane] = ((const float4*)(x + (size_t)v * DM))[lane];
            int lb = __ldg(&label[v]);
            inr[DM + lane] = lemb[lb * RD + lane];
        }
        __syncwarp();

        const float *i0 = in, *i1 = in + KIN, *i2 = in + 2 * KIN, *i3 = in + 3 * KIN;
        float4 a0 = *(float4*)(bs + c);
        float4 a1 = a0, a2 = a0, a3 = a0;
        SEG(Ws, 0, KIN)

        float4 accs[4] = {a0, a1, a2, a3};
        #pragma unroll
        for (int r = 0; r < 4; r++) {
            float4 o = accs[r];
            o.x = fmaxf(o.x, 0.f); o.y = fmaxf(o.y, 0.f);
            o.z = fmaxf(o.z, 0.f); o.w = fmaxf(o.w, 0.f);
            ((float4*)(hout + (size_t)(v0 + r) * DM))[lane] = o;
        }
    }
}

// ---------------- fused node pass: CSR gather + 3-GEMM + relu + layernorm -----
__global__ __launch_bounds__(256) void k_node_fused(
    const float* __restrict__ hin, const float* __restrict__ rel,
    const float* __restrict__ Wself, const float* __restrict__ Wn,
    const float* __restrict__ Wr, const float* __restrict__ bias,
    const float* __restrict__ lng, const float* __restrict__ lnb,
    float* __restrict__ hout)
{
    float* Ws  = smdyn;                 // DM*DM
    float* Wns = Ws + DM * DM;          // DM*DM
    float* Wrs = Wns + DM * DM;         // RD*DM
    float* bs  = Wrs + RD * DM;
    float* gs  = bs + DM;
    float* lbs = gs + DM;
    float* ins = lbs + DM;              // 8 warps * 4 rows * 288

    int tid = threadIdx.x;
    for (int i = tid; i < (DM * DM) / 4; i += 256) {
        ((float4*)Ws)[i]  = ((const float4*)Wself)[i];
        ((float4*)Wns)[i] = ((const float4*)Wn)[i];
    }
    for (int i = tid; i < (RD * DM) / 4; i += 256)
        ((float4*)Wrs)[i] = ((const float4*)Wr)[i];
    for (int i = tid; i < DM; i += 256) {
        bs[i] = bias[i]; gs[i] = lng[i]; lbs[i] = lnb[i];
    }
    __syncthreads();

    int w = tid >> 5, lane = tid & 31;
    int c = lane * 4;
    const int ntiles = NN / 4;

    for (int tile = blockIdx.x * 8 + w; tile < ntiles; tile += gridDim.x * 8) {
        int v0 = tile * 4;
        float* in = ins + w * (4 * 288);

        #pragma unroll
        for (int r = 0; r < 4; r++) {
            int v = v0 + r;
            float* inr = in + r * 288;

            // self row
            ((float4*)inr)[lane] = ((const float4*)(hin + (size_t)v * DM))[lane];

            // gather-sum neighbors
            int e   = g_off[v];
            int end = g_off[v + 1];
            float4 acc  = make_float4(0.f, 0.f, 0.f, 0.f);
            float4 acc2 = acc, aR = acc, aR2 = acc;
            while (e < end) {
                int n = min(32, end - e);
                int2 p = make_int2(0, 0);
                if (lane < n) p = g_csr[e + lane];
                int j = 0;
                for (; j + 1 < n; j += 2) {
                    int s0 = __shfl_sync(0xffffffffu, p.x, j);
                    int r0 = __shfl_sync(0xffffffffu, p.y, j);
                    int s1 = __shfl_sync(0xffffffffu, p.x, j + 1);
                    int r1 = __shfl_sync(0xffffffffu, p.y, j + 1);
                    float4 h0 = ((const float4*)(hin + (size_t)s0 * DM))[lane];
                    float4 h1 = ((const float4*)(hin + (size_t)s1 * DM))[lane];
                    float4 q0, q1;
                    if (lane < 8) {
                        q0 = ((const float4*)(rel + (size_t)r0 * RD))[lane];
                        q1 = ((const float4*)(rel + (size_t)r1 * RD))[lane];
                    }
                    acc.x  += h0.x; acc.y  += h0.y; acc.z  += h0.z; acc.w  += h0.w;
                    acc2.x += h1.x; acc2.y += h1.y; acc2.z += h1.z; acc2.w += h1.w;
                    if (lane < 8) {
                        aR.x  += q0.x; aR.y  += q0.y; aR.z  += q0.z; aR.w  += q0.w;
                        aR2.x += q1.x; aR2.y += q1.y; aR2.z += q1.z; aR2.w += q1.w;
                    }
                }
                if (j < n) {
                    int s0 = __shfl_sync(0xffffffffu, p.x, j);
                    int r0 = __shfl_sync(0xffffffffu, p.y, j);
                    float4 h0 = ((const float4*)(hin + (size_t)s0 * DM))[lane];
                    acc.x += h0.x; acc.y += h0.y; acc.z += h0.z; acc.w += h0.w;
                    if (lane < 8) {
                        float4 q0 = ((const float4*)(rel + (size_t)r0 * RD))[lane];
                        aR.x += q0.x; aR.y += q0.y; aR.z += q0.z; aR.w += q0.w;
                    }
                }
                e += n;
            }
            float iv = g_inv[v];
            acc.x = (acc.x + acc2.x) * iv; acc.y = (acc.y + acc2.y) * iv;
            acc.z = (acc.z + acc2.z) * iv; acc.w = (acc.w + acc2.w) * iv;
            ((float4*)(inr + DM))[lane] = acc;
            if (lane < 8) {
                aR.x = (aR.x + aR2.x) * iv; aR.y = (aR.y + aR2.y) * iv;
                aR.z = (aR.z + aR2.z) * iv; aR.w = (aR.w + aR2.w) * iv;
                ((float4*)(inr + 2 * DM))[lane] = aR;
            }
        }
        __syncwarp();

        const float *i0 = in, *i1 = in + 288, *i2 = in + 576, *i3 = in + 864;
        float4 a0 = *(float4*)(bs + c);
        float4 a1 = a0, a2 = a0, a3 = a0;
        SEG(Ws,  0,      DM)
        SEG(Wns, DM,     DM)
        SEG(Wrs, 2 * DM, RD)

        float4 accs[4] = {a0, a1, a2, a3};
        #pragma unroll
        for (int r = 0; r < 4; r++) {
            float4 o = accs[r];
            o.x = fmaxf(o.x, 0.f); o.y = fmaxf(o.y, 0.f);
            o.z = fmaxf(o.z, 0.f); o.w = fmaxf(o.w, 0.f);

            float s1 = o.x + o.y + o.z + o.w;
            float s2 = o.x * o.x + o.y * o.y + o.z * o.z + o.w * o.w;
            #pragma unroll
            for (int off = 16; off > 0; off >>= 1) {
                s1 += __shfl_xor_sync(0xffffffffu, s1, off);
                s2 += __shfl_xor_sync(0xffffffffu, s2, off);
            }
            float mu  = s1 * (1.f / 128.f);
            float var = s2 * (1.f / 128.f) - mu * mu;
            float rs  = rsqrtf(var + LN_EPS);

            float4 o4;
            o4.x = (o.x - mu) * rs * gs[c + 0] + lbs[c + 0];
            o4.y = (o.y - mu) * rs * gs[c + 1] + lbs[c + 1];
            o4.z = (o.z - mu) * rs * gs[c + 2] + lbs[c + 2];
            o4.w = (o.w - mu) * rs * gs[c + 3] + lbs[c + 3];
            ((float4*)(hout + (size_t)(v0 + r) * DM))[lane] = o4;
        }
    }
}

// ---------------- host launch --------------------------------------------------
extern "C" void kernel_launch(void* const* d_in, const int* in_sizes, int n_in,
                              void* d_out, int out_size)
{
    const float* x      = (const float*)d_in[0];
    const int*   label  = (const int*)d_in[1];
    const int*   eidx   = (const int*)d_in[2];
    const int*   erel   = (const int*)d_in[3];
    const float* lemb   = (const float*)d_in[4];
    const float* Win    = (const float*)d_in[5];
    const float* bin    = (const float*)d_in[6];
    const float* relemb = (const float*)d_in[7];
    const float* Wn     = (const float*)d_in[8];
    const float* Wself  = (const float*)d_in[9];
    const float* bself  = (const float*)d_in[10];
    const float* Wr     = (const float*)d_in[11];
    const float* lng    = (const float*)d_in[12];
    const float* lnb    = (const float*)d_in[13];
    float* out = (float*)d_out;

    float *p_h, *p_h2;
    int *p_deg;
    cudaGetSymbolAddress((void**)&p_h,   g_h);
    cudaGetSymbolAddress((void**)&p_h2,  g_h2);
    cudaGetSymbolAddress((void**)&p_deg, g_deg);

    const int smemI = (KIN * DM + DM + 8 * 4 * KIN) * sizeof(float);
    const int smemN = (2 * DM * DM + RD * DM + 3 * DM + 8 * 4 * 288) * sizeof(float);
    cudaFuncSetAttribute(k_input,      cudaFuncAttributeMaxDynamicSharedMemorySize, smemI);
    cudaFuncSetAttribute(k_node_fused, cudaFuncAttributeMaxDynamicSharedMemorySize, smemN);

    // CSR build
    k_zero_int<<<(NN + 255) / 256, 256>>>(p_deg, NN);
    k_deg<<<(EE + 255) / 256, 256>>>(eidx + EE);
    k_scan<<<1, 1024>>>();
    k_scatter<<<(EE + 255) / 256, 256>>>(eidx, eidx + EE, erel);

    // input projection (overlaps nothing it depends on incorrectly; stream order)
    k_input<<<148, 256, smemI>>>(x, label, lemb, Win, bin, p_h);

    const float* hin = p_h;
    for (int l = 0; l < 2; l++) {
        float* hout = (l == 0) ? p_h2 : out;
        k_node_fused<<<148, 256, smemN>>>(hin, relemb + l * 1024 * RD,
                                          Wself + l * DM * DM, Wn + l * DM * DM,
                                          Wr + l * RD * DM, bself + l * DM,
                                          lng + l * DM, lnb + l * DM, hout);
        hin = hout;
    }
}

// round 4
// speedup vs baseline: 1.0447x; 1.0447x over previous
#include <cuda_runtime.h>

#define NN 50000
#define EE 800000
#define DM 128
#define RD 32
#define KIN 160
#define LN_EPS 1e-5f

// ---------------- scratch ----------------------------------------------------
__device__ float g_h[NN * DM];
__device__ float g_h2[NN * DM];
__device__ float g_aggH[NN * DM];
__device__ float g_aggR[NN * RD];
__device__ float g_inv[NN];
__device__ int   g_deg[NN];
__device__ int   g_off[NN + 1];
__device__ int   g_cur[NN];
__device__ int2  g_csr[EE];        // (src, rel) grouped by dst

// ---------------- CSR build ----------------------------------------------------
__global__ void k_zero_int(int* __restrict__ p, int n) {
    int i = blockIdx.x * blockDim.x + threadIdx.x;
    if (i < n) p[i] = 0;
}

__global__ void k_deg(const int* __restrict__ dst) {
    int i = blockIdx.x * blockDim.x + threadIdx.x;
    if (i < EE) atomicAdd(&g_deg[dst[i]], 1);
}

__global__ __launch_bounds__(1024) void k_scan() {
    __shared__ int warp_sums[32];
    const int CH = (NN + 1023) / 1024;
    int t = threadIdx.x, lane = t & 31, w = t >> 5;
    int base = t * CH;
    int s = 0;
    for (int i = 0; i < CH; i++) {
        int idx = base + i;
        if (idx < NN) s += g_deg[idx];
    }
    int v = s;
    #pragma unroll
    for (int o = 1; o < 32; o <<= 1) {
        int u = __shfl_up_sync(0xffffffffu, v, o);
        if (lane >= o) v += u;
    }
    if (lane == 31) warp_sums[w] = v;
    __syncthreads();
    if (w == 0) {
        int u = warp_sums[lane];
        #pragma unroll
        for (int o = 1; o < 32; o <<= 1) {
            int uu = __shfl_up_sync(0xffffffffu, u, o);
            if (lane >= o) u += uu;
        }
        warp_sums[lane] = u;
    }
    __syncthreads();
    int excl = v - s + (w > 0 ? warp_sums[w - 1] : 0);
    int run = excl;
    for (int i = 0; i < CH; i++) {
        int idx = base + i;
        if (idx < NN) {
            int d = g_deg[idx];
            g_off[idx] = run;
            g_cur[idx] = run;
            g_inv[idx] = d > 0 ? (1.f / (float)d) : 0.f;
            run += d;
        }
    }
    if (t == 0) g_off[NN] = EE;
}

__global__ void k_scatter(const int* __restrict__ src, const int* __restrict__ dst,
                          const int* __restrict__ erel) {
    int i = blockIdx.x * blockDim.x + threadIdx.x;
    if (i < EE) {
        int d = dst[i];
        int pos = atomicAdd(&g_cur[d], 1);
        g_csr[pos] = make_int2(src[i], erel[i]);
    }
}

// ---------------- gather: aggH[v]=mean h[src], aggR[v]=mean rel[erel] ----------
__global__ __launch_bounds__(256) void k_gather(
    const float* __restrict__ hin, const float* __restrict__ rel)
{
    int warp = (blockIdx.x * blockDim.x + threadIdx.x) >> 5;
    int lane = threadIdx.x & 31;
    if (warp >= NN) return;
    int v = warp;

    int e = g_off[v], end = g_off[v + 1];
    float4 acc  = make_float4(0.f, 0.f, 0.f, 0.f);
    float4 acc2 = acc, aR = acc, aR2 = acc;
    while (e < end) {
        int n = min(32, end - e);
        int2 p = make_int2(0, 0);
        if (lane < n) p = g_csr[e + lane];
        int j = 0;
        for (; j + 1 < n; j += 2) {
            int s0 = __shfl_sync(0xffffffffu, p.x, j);
            int r0 = __shfl_sync(0xffffffffu, p.y, j);
            int s1 = __shfl_sync(0xffffffffu, p.x, j + 1);
            int r1 = __shfl_sync(0xffffffffu, p.y, j + 1);
            float4 h0 = ((const float4*)(hin + (size_t)s0 * DM))[lane];
            float4 h1 = ((const float4*)(hin + (size_t)s1 * DM))[lane];
            float4 q0, q1;
            if (lane < 8) {
                q0 = ((const float4*)(rel + (size_t)r0 * RD))[lane];
                q1 = ((const float4*)(rel + (size_t)r1 * RD))[lane];
            }
            acc.x  += h0.x; acc.y  += h0.y; acc.z  += h0.z; acc.w  += h0.w;
            acc2.x += h1.x; acc2.y += h1.y; acc2.z += h1.z; acc2.w += h1.w;
            if (lane < 8) {
                aR.x  += q0.x; aR.y  += q0.y; aR.z  += q0.z; aR.w  += q0.w;
                aR2.x += q1.x; aR2.y += q1.y; aR2.z += q1.z; aR2.w += q1.w;
            }
        }
        if (j < n) {
            int s0 = __shfl_sync(0xffffffffu, p.x, j);
            int r0 = __shfl_sync(0xffffffffu, p.y, j);
            float4 h0 = ((const float4*)(hin + (size_t)s0 * DM))[lane];
            acc.x += h0.x; acc.y += h0.y; acc.z += h0.z; acc.w += h0.w;
            if (lane < 8) {
                float4 q0 = ((const float4*)(rel + (size_t)r0 * RD))[lane];
                aR.x += q0.x; aR.y += q0.y; aR.z += q0.z; aR.w += q0.w;
            }
        }
        e += n;
    }
    float iv = g_inv[v];
    acc.x = (acc.x + acc2.x) * iv; acc.y = (acc.y + acc2.y) * iv;
    acc.z = (acc.z + acc2.z) * iv; acc.w = (acc.w + acc2.w) * iv;
    ((float4*)(g_aggH + (size_t)v * DM))[lane] = acc;
    if (lane < 8) {
        aR.x = (aR.x + aR2.x) * iv; aR.y = (aR.y + aR2.y) * iv;
        aR.z = (aR.z + aR2.z) * iv; aR.w = (aR.w + aR2.w) * iv;
        ((float4*)(g_aggR + (size_t)v * RD))[lane] = aR;
    }
}

// ---------------- packed fp32 GEMM machinery -----------------------------------
extern __shared__ float smdyn[];

#define PFMA(D, A, B) \
    asm("fma.rn.f32x2 %0, %1, %2, %0;" : "+l"(D) : "l"(A), "l"(B));

__device__ __forceinline__ float phsum(unsigned long long v) {
    float lo = __uint_as_float((unsigned)v);
    float hi = __uint_as_float((unsigned)(v >> 32));
    return lo + hi;
}

// stage K x DM row-major weight into k-pair-interleaved layout:
// Wp[kp*2*DM + c*2 + 0] = W[2kp][c], +1 = W[2kp+1][c]
#define STAGE_PAIRS(Wp, W, K)                                          \
    for (int idx = tid; idx < ((K) / 2) * (DM / 4); idx += 256) {      \
        int kp = idx / (DM / 4);                                       \
        int cc = (idx % (DM / 4)) * 4;                                 \
        float4 g0 = ((const float4*)((W) + (2 * kp) * DM + cc))[0];    \
        float4 g1 = ((const float4*)((W) + (2 * kp + 1) * DM + cc))[0];\
        float* dp = (Wp) + kp * 2 * DM + cc * 2;                       \
        ((float4*)dp)[0] = make_float4(g0.x, g1.x, g0.y, g1.y);        \
        ((float4*)dp)[1] = make_float4(g0.z, g1.z, g0.w, g1.w);        \
    }

#define PROW(R0, R1, R2, R3, BX, BY)   \
    PFMA(R0, BX, wA0.x) PFMA(R1, BX, wA0.y) PFMA(R2, BX, wB0.x) PFMA(R3, BX, wB0.y) \
    PFMA(R0, BY, wA1.x) PFMA(R1, BY, wA1.y) PFMA(R2, BY, wB1.x) PFMA(R3, BY, wB1.y)

#define SEG2(Wb, OFF, LEN)                                                   \
    _Pragma("unroll 4")                                                      \
    for (int k = 0; k < (LEN); k += 4) {                                     \
        ulonglong2 b0 = *(const ulonglong2*)(i0 + (OFF) + k);                \
        ulonglong2 b1 = *(const ulonglong2*)(i1 + (OFF) + k);                \
        ulonglong2 b2 = *(const ulonglong2*)(i2 + (OFF) + k);                \
        ulonglong2 b3 = *(const ulonglong2*)(i3 + (OFF) + k);                \
        const float* wb = (Wb) + k * DM + (c << 1);                          \
        ulonglong2 wA0 = *(const ulonglong2*)(wb);                           \
        ulonglong2 wB0 = *(const ulonglong2*)(wb + 4);                       \
        ulonglong2 wA1 = *(const ulonglong2*)(wb + 2 * DM);                  \
        ulonglong2 wB1 = *(const ulonglong2*)(wb + 2 * DM + 4);              \
        PROW(A00, A01, A02, A03, b0.x, b0.y)                                 \
        PROW(A10, A11, A12, A13, b1.x, b1.y)                                 \
        PROW(A20, A21, A22, A23, b2.x, b2.y)                                 \
        PROW(A30, A31, A32, A33, b3.x, b3.y)                                 \
    }

#define DECL_ACC                                                    \
    unsigned long long A00 = 0, A01 = 0, A02 = 0, A03 = 0,          \
                       A10 = 0, A11 = 0, A12 = 0, A13 = 0,          \
                       A20 = 0, A21 = 0, A22 = 0, A23 = 0,          \
                       A30 = 0, A31 = 0, A32 = 0, A33 = 0;

// ---------------- input projection ----------------------------------------------
__global__ __launch_bounds__(256) void k_input(
    const float* __restrict__ x, const int* __restrict__ label,
    const float* __restrict__ lemb, const float* __restrict__ W,
    const float* __restrict__ b, float* __restrict__ hout)
{
    float* Ws  = smdyn;             // KIN*DM (pair-interleaved)
    float* bs  = Ws + KIN * DM;
    float* ins = bs + DM;
    int tid = threadIdx.x;

    STAGE_PAIRS(Ws, W, KIN)
    for (int i = tid; i < DM; i += 256) bs[i] = b[i];
    __syncthreads();

    int w = tid >> 5, lane = tid & 31;
    int c = lane * 4;
    const int ntiles = NN / 4;

    for (int tile = blockIdx.x * 8 + w; tile < ntiles; tile += gridDim.x * 8) {
        int v0 = tile * 4;
        float* in = ins + w * (4 * KIN);
        #pragma unroll
        for (int r = 0; r < 4; r++) {
            int v = v0 + r;
            float* inr = in + r * KIN;
            ((float4*)inr)[lane] = ((const float4*)(x + (size_t)v * DM))[lane];
            int lb = __ldg(&label[v]);
            inr[DM + lane] = lemb[lb * RD + lane];
        }
        __syncwarp();

        const float *i0 = in, *i1 = in + KIN, *i2 = in + 2 * KIN, *i3 = in + 3 * KIN;
        DECL_ACC
        SEG2(Ws, 0, KIN)

        float4 bb = *(float4*)(bs + c);
        float4 o;
        o.x = fmaxf(phsum(A00) + bb.x, 0.f); o.y = fmaxf(phsum(A01) + bb.y, 0.f);
        o.z = fmaxf(phsum(A02) + bb.z, 0.f); o.w = fmaxf(phsum(A03) + bb.w, 0.f);
        ((float4*)(hout + (size_t)v0 * DM))[lane] = o;
        o.x = fmaxf(phsum(A10) + bb.x, 0.f); o.y = fmaxf(phsum(A11) + bb.y, 0.f);
        o.z = fmaxf(phsum(A12) + bb.z, 0.f); o.w = fmaxf(phsum(A13) + bb.w, 0.f);
        ((float4*)(hout + (size_t)(v0 + 1) * DM))[lane] = o;
        o.x = fmaxf(phsum(A20) + bb.x, 0.f); o.y = fmaxf(phsum(A21) + bb.y, 0.f);
        o.z = fmaxf(phsum(A22) + bb.z, 0.f); o.w = fmaxf(phsum(A23) + bb.w, 0.f);
        ((float4*)(hout + (size_t)(v0 + 2) * DM))[lane] = o;
        o.x = fmaxf(phsum(A30) + bb.x, 0.f); o.y = fmaxf(phsum(A31) + bb.y, 0.f);
        o.z = fmaxf(phsum(A32) + bb.z, 0.f); o.w = fmaxf(phsum(A33) + bb.w, 0.f);
        ((float4*)(hout + (size_t)(v0 + 3) * DM))[lane] = o;
    }
}

// ---------------- node pass: 3-GEMM + bias + relu + layernorm --------------------
__global__ __launch_bounds__(256) void k_node(
    const float* __restrict__ hin,
    const float* __restrict__ Wself, const float* __restrict__ Wn,
    const float* __restrict__ Wr, const float* __restrict__ bias,
    const float* __restrict__ lng, const float* __restrict__ lnb,
    float* __restrict__ hout)
{
    float* Ws  = smdyn;                 // DM*DM pair-interleaved
    float* Wns = Ws + DM * DM;
    float* Wrs = Wns + DM * DM;         // RD*DM
    float* bs  = Wrs + RD * DM;
    float* gs  = bs + DM;
    float* lbs = gs + DM;
    float* ins = lbs + DM;              // 8 warps * 4 rows * 288

    int tid = threadIdx.x;
    STAGE_PAIRS(Ws,  Wself, DM)
    STAGE_PAIRS(Wns, Wn,    DM)
    STAGE_PAIRS(Wrs, Wr,    RD)
    for (int i = tid; i < DM; i += 256) {
        bs[i] = bias[i]; gs[i] = lng[i]; lbs[i] = lnb[i];
    }
    __syncthreads();

    int w = tid >> 5, lane = tid & 31;
    int c = lane * 4;
    const int ntiles = NN / 4;

    for (int tile = blockIdx.x * 8 + w; tile < ntiles; tile += gridDim.x * 8) {
        int v0 = tile * 4;
        float* in = ins + w * (4 * 288);
        #pragma unroll
        for (int r = 0; r < 4; r++) {
            int v = v0 + r;
            float* inr = in + r * 288;
            ((float4*)inr)[lane]        = ((const float4*)(hin + (size_t)v * DM))[lane];
            ((float4*)(inr + DM))[lane] = ((const float4*)(g_aggH + (size_t)v * DM))[lane];
            if (lane < 8)
                ((float4*)(inr + 2 * DM))[lane] = ((const float4*)(g_aggR + (size_t)v * RD))[lane];
        }
        __syncwarp();

        const float *i0 = in, *i1 = in + 288, *i2 = in + 576, *i3 = in + 864;
        DECL_ACC
        SEG2(Ws,  0,      DM)
        SEG2(Wns, DM,     DM)
        SEG2(Wrs, 2 * DM, RD)

        float4 bb = *(float4*)(bs + c);
        float4 accs[4];
        accs[0] = make_float4(phsum(A00) + bb.x, phsum(A01) + bb.y, phsum(A02) + bb.z, phsum(A03) + bb.w);
        accs[1] = make_float4(phsum(A10) + bb.x, phsum(A11) + bb.y, phsum(A12) + bb.z, phsum(A13) + bb.w);
        accs[2] = make_float4(phsum(A20) + bb.x, phsum(A21) + bb.y, phsum(A22) + bb.z, phsum(A23) + bb.w);
        accs[3] = make_float4(phsum(A30) + bb.x, phsum(A31) + bb.y, phsum(A32) + bb.z, phsum(A33) + bb.w);

        #pragma unroll
        for (int r = 0; r < 4; r++) {
            float4 o = accs[r];
            o.x = fmaxf(o.x, 0.f); o.y = fmaxf(o.y, 0.f);
            o.z = fmaxf(o.z, 0.f); o.w = fmaxf(o.w, 0.f);

            float s1 = o.x + o.y + o.z + o.w;
            float s2 = o.x * o.x + o.y * o.y + o.z * o.z + o.w * o.w;
            #pragma unroll
            for (int off = 16; off > 0; off >>= 1) {
                s1 += __shfl_xor_sync(0xffffffffu, s1, off);
                s2 += __shfl_xor_sync(0xffffffffu, s2, off);
            }
            float mu  = s1 * (1.f / 128.f);
            float var = s2 * (1.f / 128.f) - mu * mu;
            float rs  = rsqrtf(var + LN_EPS);

            float4 o4;
            o4.x = (o.x - mu) * rs * gs[c + 0] + lbs[c + 0];
            o4.y = (o.y - mu) * rs * gs[c + 1] + lbs[c + 1];
            o4.z = (o.z - mu) * rs * gs[c + 2] + lbs[c + 2];
            o4.w = (o.w - mu) * rs * gs[c + 3] + lbs[c + 3];
            ((float4*)(hout + (size_t)(v0 + r) * DM))[lane] = o4;
        }
    }
}

// ---------------- host launch ------------------------------------------------------
extern "C" void kernel_launch(void* const* d_in, const int* in_sizes, int n_in,
                              void* d_out, int out_size)
{
    const float* x      = (const float*)d_in[0];
    const int*   label  = (const int*)d_in[1];
    const int*   eidx   = (const int*)d_in[2];
    const int*   erel   = (const int*)d_in[3];
    const float* lemb   = (const float*)d_in[4];
    const float* Win    = (const float*)d_in[5];
    const float* bin    = (const float*)d_in[6];
    const float* relemb = (const float*)d_in[7];
    const float* Wn     = (const float*)d_in[8];
    const float* Wself  = (const float*)d_in[9];
    const float* bself  = (const float*)d_in[10];
    const float* Wr     = (const float*)d_in[11];
    const float* lng    = (const float*)d_in[12];
    const float* lnb    = (const float*)d_in[13];
    float* out = (float*)d_out;

    float *p_h, *p_h2;
    int *p_deg;
    cudaGetSymbolAddress((void**)&p_h,   g_h);
    cudaGetSymbolAddress((void**)&p_h2,  g_h2);
    cudaGetSymbolAddress((void**)&p_deg, g_deg);

    const int smemI = (KIN * DM + DM + 8 * 4 * KIN) * sizeof(float);
    const int smemN = (2 * DM * DM + RD * DM + 3 * DM + 8 * 4 * 288) * sizeof(float);
    cudaFuncSetAttribute(k_input, cudaFuncAttributeMaxDynamicSharedMemorySize, smemI);
    cudaFuncSetAttribute(k_node,  cudaFuncAttributeMaxDynamicSharedMemorySize, smemN);

    // CSR build
    k_zero_int<<<(NN + 255) / 256, 256>>>(p_deg, NN);
    k_deg<<<(EE + 255) / 256, 256>>>(eidx + EE);
    k_scan<<<1, 1024>>>();
    k_scatter<<<(EE + 255) / 256, 256>>>(eidx, eidx + EE, erel);

    // input projection
    k_input<<<148, 256, smemI>>>(x, label, lemb, Win, bin, p_h);

    const float* hin = p_h;
    for (int l = 0; l < 2; l++) {
        float* hout = (l == 0) ? p_h2 : out;
        k_gather<<<(NN * 32 + 255) / 256, 256>>>(hin, relemb + l * 1024 * RD);
        k_node<<<148, 256, smemN>>>(hin,
                                    Wself + l * DM * DM, Wn + l * DM * DM,
                                    Wr + l * RD * DM, bself + l * DM,
                                    lng + l * DM, lnb + l * DM, hout);
        hin = hout;
    }
}

// round 5
// speedup vs baseline: 1.2398x; 1.1868x over previous
#include <cuda_runtime.h>

#define NN 50000
#define EE 800000
#define DM 128
#define RD 32
#define KIN 160
#define LN_EPS 1e-5f

// ---------------- scratch ----------------------------------------------------
__device__ float g_h[NN * DM];
__device__ float g_h2[NN * DM];
__device__ float g_aggH[NN * DM];
__device__ float g_aggR[NN * RD];
__device__ float g_inv[NN];
__device__ int   g_deg[NN];
__device__ int   g_off[NN + 1];
__device__ int   g_cur[NN];
__device__ int2  g_csr[EE];        // (src, rel) grouped by dst

// ---------------- CSR build ----------------------------------------------------
__global__ void k_zero_int(int* __restrict__ p, int n) {
    int i = blockIdx.x * blockDim.x + threadIdx.x;
    if (i < n) p[i] = 0;
}

__global__ void k_deg(const int* __restrict__ dst) {
    int i = blockIdx.x * blockDim.x + threadIdx.x;
    if (i < EE) atomicAdd(&g_deg[dst[i]], 1);
}

__global__ __launch_bounds__(1024) void k_scan() {
    __shared__ int warp_sums[32];
    const int CH = (NN + 1023) / 1024;
    int t = threadIdx.x, lane = t & 31, w = t >> 5;
    int base = t * CH;
    int s = 0;
    for (int i = 0; i < CH; i++) {
        int idx = base + i;
        if (idx < NN) s += g_deg[idx];
    }
    int v = s;
    #pragma unroll
    for (int o = 1; o < 32; o <<= 1) {
        int u = __shfl_up_sync(0xffffffffu, v, o);
        if (lane >= o) v += u;
    }
    if (lane == 31) warp_sums[w] = v;
    __syncthreads();
    if (w == 0) {
        int u = warp_sums[lane];
        #pragma unroll
        for (int o = 1; o < 32; o <<= 1) {
            int uu = __shfl_up_sync(0xffffffffu, u, o);
            if (lane >= o) u += uu;
        }
        warp_sums[lane] = u;
    }
    __syncthreads();
    int excl = v - s + (w > 0 ? warp_sums[w - 1] : 0);
    int run = excl;
    for (int i = 0; i < CH; i++) {
        int idx = base + i;
        if (idx < NN) {
            int d = g_deg[idx];
            g_off[idx] = run;
            g_cur[idx] = run;
            g_inv[idx] = d > 0 ? (1.f / (float)d) : 0.f;
            run += d;
        }
    }
    if (t == 0) g_off[NN] = EE;
}

__global__ void k_scatter(const int* __restrict__ src, const int* __restrict__ dst,
                          const int* __restrict__ erel) {
    int i = blockIdx.x * blockDim.x + threadIdx.x;
    if (i < EE) {
        int d = dst[i];
        int pos = atomicAdd(&g_cur[d], 1);
        g_csr[pos] = make_int2(src[i], erel[i]);
    }
}

// ---------------- gather: aggH[v]=mean h[src], aggR[v]=mean rel[erel] ----------
__global__ __launch_bounds__(256) void k_gather(
    const float* __restrict__ hin, const float* __restrict__ rel)
{
    __shared__ int2 stage[8][32];
    int w = threadIdx.x >> 5, lane = threadIdx.x & 31;
    int v = blockIdx.x * 8 + w;
    if (v >= NN) return;
    int2* st = stage[w];

    int e = g_off[v], end = g_off[v + 1];
    float4 a0 = make_float4(0.f, 0.f, 0.f, 0.f), a1 = a0, a2 = a0, a3 = a0;
    float r0s = 0.f, r1s = 0.f, r2s = 0.f, r3s = 0.f;

    while (e < end) {
        int n = min(32, end - e);
        if (lane < n) st[lane] = g_csr[e + lane];
        __syncwarp();
        int j = 0;
        for (; j + 4 <= n; j += 4) {
            int2 p0 = st[j], p1 = st[j + 1], p2 = st[j + 2], p3 = st[j + 3];
            float4 h0 = ((const float4*)(hin + (size_t)p0.x * DM))[lane];
            float4 h1 = ((const float4*)(hin + (size_t)p1.x * DM))[lane];
            float4 h2 = ((const float4*)(hin + (size_t)p2.x * DM))[lane];
            float4 h3 = ((const float4*)(hin + (size_t)p3.x * DM))[lane];
            float q0 = rel[p0.y * RD + lane];
            float q1 = rel[p1.y * RD + lane];
            float q2 = rel[p2.y * RD + lane];
            float q3 = rel[p3.y * RD + lane];
            a0.x += h0.x; a0.y += h0.y; a0.z += h0.z; a0.w += h0.w;
            a1.x += h1.x; a1.y += h1.y; a1.z += h1.z; a1.w += h1.w;
            a2.x += h2.x; a2.y += h2.y; a2.z += h2.z; a2.w += h2.w;
            a3.x += h3.x; a3.y += h3.y; a3.z += h3.z; a3.w += h3.w;
            r0s += q0; r1s += q1; r2s += q2; r3s += q3;
        }
        for (; j < n; j++) {
            int2 p0 = st[j];
            float4 h0 = ((const float4*)(hin + (size_t)p0.x * DM))[lane];
            a0.x += h0.x; a0.y += h0.y; a0.z += h0.z; a0.w += h0.w;
            r0s += rel[p0.y * RD + lane];
        }
        e += n;
        __syncwarp();
    }

    float iv = g_inv[v];
    float4 acc;
    acc.x = (a0.x + a1.x + a2.x + a3.x) * iv;
    acc.y = (a0.y + a1.y + a2.y + a3.y) * iv;
    acc.z = (a0.z + a1.z + a2.z + a3.z) * iv;
    acc.w = (a0.w + a1.w + a2.w + a3.w) * iv;
    ((float4*)(g_aggH + (size_t)v * DM))[lane] = acc;
    g_aggR[v * RD + lane] = (r0s + r1s + r2s + r3s) * iv;
}

// ---------------- packed fp32 GEMM machinery -----------------------------------
extern __shared__ float smdyn[];

#define PFMA(D, A, B) \
    asm("fma.rn.f32x2 %0, %1, %2, %0;" : "+l"(D) : "l"(A), "l"(B));

__device__ __forceinline__ float phsum(unsigned long long v) {
    float lo = __uint_as_float((unsigned)v);
    float hi = __uint_as_float((unsigned)(v >> 32));
    return lo + hi;
}

// Stage K x DM row-major weight into conflict-free k-pair layout.
// For each k-pair kp (rows 2kp, 2kp+1), region of 2*DM floats at kp*2*DM:
//   A half (cols with col%4 in {0,1}): lane l gets 16B at [l*4..l*4+3] =
//       {W[2kp][4l], W[2kp+1][4l], W[2kp][4l+1], W[2kp+1][4l+1]}
//   B half (cols with col%4 in {2,3}) at +DM, same per-lane 16B density.
// All GEMM weight LDS.128s are then 16B/lane dense -> conflict-free.
#define STAGE_PAIRS(Wp, W, K)                                              \
    for (int idx = tid; idx < ((K) / 2) * DM; idx += 256) {                \
        int kp  = idx / DM;                                                \
        int col = idx % DM;                                                \
        float w0 = (W)[(2 * kp) * DM + col];                               \
        float w1 = (W)[(2 * kp + 1) * DM + col];                           \
        int dst = kp * 2 * DM + ((col & 2) ? DM : 0)                       \
                + ((col >> 2) << 2) + ((col & 1) << 1);                    \
        (Wp)[dst] = w0; (Wp)[dst + 1] = w1;                                \
    }

#define PROW(R0, R1, R2, R3, BX, BY)   \
    PFMA(R0, BX, wA0.x) PFMA(R1, BX, wA0.y) PFMA(R2, BX, wB0.x) PFMA(R3, BX, wB0.y) \
    PFMA(R0, BY, wA1.x) PFMA(R1, BY, wA1.y) PFMA(R2, BY, wB1.x) PFMA(R3, BY, wB1.y)

// kp region for k..k+1 lives at float offset k*DM (since region = 2*DM floats)
#define SEG2(Wb, OFF, LEN)                                                   \
    _Pragma("unroll 4")                                                      \
    for (int k = 0; k < (LEN); k += 4) {                                     \
        ulonglong2 b0 = *(const ulonglong2*)(i0 + (OFF) + k);                \
        ulonglong2 b1 = *(const ulonglong2*)(i1 + (OFF) + k);                \
        ulonglong2 b2 = *(const ulonglong2*)(i2 + (OFF) + k);                \
        ulonglong2 b3 = *(const ulonglong2*)(i3 + (OFF) + k);                \
        const float* wb = (Wb) + k * DM + c;                                 \
        ulonglong2 wA0 = *(const ulonglong2*)(wb);                           \
        ulonglong2 wB0 = *(const ulonglong2*)(wb + DM);                      \
        ulonglong2 wA1 = *(const ulonglong2*)(wb + 2 * DM);                  \
        ulonglong2 wB1 = *(const ulonglong2*)(wb + 3 * DM);                  \
        PROW(A00, A01, A02, A03, b0.x, b0.y)                                 \
        PROW(A10, A11, A12, A13, b1.x, b1.y)                                 \
        PROW(A20, A21, A22, A23, b2.x, b2.y)                                 \
        PROW(A30, A31, A32, A33, b3.x, b3.y)                                 \
    }

#define DECL_ACC                                                    \
    unsigned long long A00 = 0, A01 = 0, A02 = 0, A03 = 0,          \
                       A10 = 0, A11 = 0, A12 = 0, A13 = 0,          \
                       A20 = 0, A21 = 0, A22 = 0, A23 = 0,          \
                       A30 = 0, A31 = 0, A32 = 0, A33 = 0;

// ---------------- input projection ----------------------------------------------
__global__ __launch_bounds__(256) void k_input(
    const float* __restrict__ x, const int* __restrict__ label,
    const float* __restrict__ lemb, const float* __restrict__ W,
    const float* __restrict__ b, float* __restrict__ hout)
{
    float* Ws  = smdyn;             // KIN*DM (pair layout)
    float* bs  = Ws + KIN * DM;
    float* ins = bs + DM;
    int tid = threadIdx.x;

    STAGE_PAIRS(Ws, W, KIN)
    for (int i = tid; i < DM; i += 256) bs[i] = b[i];
    __syncthreads();

    int w = tid >> 5, lane = tid & 31;
    int c = lane * 4;
    const int ntiles = NN / 4;

    for (int tile = blockIdx.x * 8 + w; tile < ntiles; tile += gridDim.x * 8) {
        int v0 = tile * 4;
        float* in = ins + w * (4 * KIN);
        #pragma unroll
        for (int r = 0; r < 4; r++) {
            int v = v0 + r;
            float* inr = in + r * KIN;
            ((float4*)inr)[lane] = ((const float4*)(x + (size_t)v * DM))[lane];
            int lb = __ldg(&label[v]);
            inr[DM + lane] = lemb[lb * RD + lane];
        }
        __syncwarp();

        const float *i0 = in, *i1 = in + KIN, *i2 = in + 2 * KIN, *i3 = in + 3 * KIN;
        DECL_ACC
        SEG2(Ws, 0, KIN)

        float4 bb = *(float4*)(bs + c);
        float4 o;
        o.x = fmaxf(phsum(A00) + bb.x, 0.f); o.y = fmaxf(phsum(A01) + bb.y, 0.f);
        o.z = fmaxf(phsum(A02) + bb.z, 0.f); o.w = fmaxf(phsum(A03) + bb.w, 0.f);
        ((float4*)(hout + (size_t)v0 * DM))[lane] = o;
        o.x = fmaxf(phsum(A10) + bb.x, 0.f); o.y = fmaxf(phsum(A11) + bb.y, 0.f);
        o.z = fmaxf(phsum(A12) + bb.z, 0.f); o.w = fmaxf(phsum(A13) + bb.w, 0.f);
        ((float4*)(hout + (size_t)(v0 + 1) * DM))[lane] = o;
        o.x = fmaxf(phsum(A20) + bb.x, 0.f); o.y = fmaxf(phsum(A21) + bb.y, 0.f);
        o.z = fmaxf(phsum(A22) + bb.z, 0.f); o.w = fmaxf(phsum(A23) + bb.w, 0.f);
        ((float4*)(hout + (size_t)(v0 + 2) * DM))[lane] = o;
        o.x = fmaxf(phsum(A30) + bb.x, 0.f); o.y = fmaxf(phsum(A31) + bb.y, 0.f);
        o.z = fmaxf(phsum(A32) + bb.z, 0.f); o.w = fmaxf(phsum(A33) + bb.w, 0.f);
        ((float4*)(hout + (size_t)(v0 + 3) * DM))[lane] = o;
    }
}

// ---------------- node pass: 3-GEMM + bias + relu + layernorm --------------------
__global__ __launch_bounds__(256) void k_node(
    const float* __restrict__ hin,
    const float* __restrict__ Wself, const float* __restrict__ Wn,
    const float* __restrict__ Wr, const float* __restrict__ bias,
    const float* __restrict__ lng, const float* __restrict__ lnb,
    float* __restrict__ hout)
{
    float* Ws  = smdyn;                 // DM*DM pair layout
    float* Wns = Ws + DM * DM;
    float* Wrs = Wns + DM * DM;         // RD*DM
    float* bs  = Wrs + RD * DM;
    float* gs  = bs + DM;
    float* lbs = gs + DM;
    float* ins = lbs + DM;              // 8 warps * 4 rows * 288

    int tid = threadIdx.x;
    STAGE_PAIRS(Ws,  Wself, DM)
    STAGE_PAIRS(Wns, Wn,    DM)
    STAGE_PAIRS(Wrs, Wr,    RD)
    for (int i = tid; i < DM; i += 256) {
        bs[i] = bias[i]; gs[i] = lng[i]; lbs[i] = lnb[i];
    }
    __syncthreads();

    int w = tid >> 5, lane = tid & 31;
    int c = lane * 4;
    const int ntiles = NN / 4;

    for (int tile = blockIdx.x * 8 + w; tile < ntiles; tile += gridDim.x * 8) {
        int v0 = tile * 4;
        float* in = ins + w * (4 * 288);
        #pragma unroll
        for (int r = 0; r < 4; r++) {
            int v = v0 + r;
            float* inr = in + r * 288;
            ((float4*)inr)[lane]        = ((const float4*)(hin + (size_t)v * DM))[lane];
            ((float4*)(inr + DM))[lane] = ((const float4*)(g_aggH + (size_t)v * DM))[lane];
            inr[2 * DM + lane]          = g_aggR[v * RD + lane];
        }
        __syncwarp();

        const float *i0 = in, *i1 = in + 288, *i2 = in + 576, *i3 = in + 864;
        DECL_ACC
        SEG2(Ws,  0,      DM)
        SEG2(Wns, DM,     DM)
        SEG2(Wrs, 2 * DM, RD)

        float4 bb = *(float4*)(bs + c);
        float4 accs[4];
        accs[0] = make_float4(phsum(A00) + bb.x, phsum(A01) + bb.y, phsum(A02) + bb.z, phsum(A03) + bb.w);
        accs[1] = make_float4(phsum(A10) + bb.x, phsum(A11) + bb.y, phsum(A12) + bb.z, phsum(A13) + bb.w);
        accs[2] = make_float4(phsum(A20) + bb.x, phsum(A21) + bb.y, phsum(A22) + bb.z, phsum(A23) + bb.w);
        accs[3] = make_float4(phsum(A30) + bb.x, phsum(A31) + bb.y, phsum(A32) + bb.z, phsum(A33) + bb.w);

        #pragma unroll
        for (int r = 0; r < 4; r++) {
            float4 o = accs[r];
            o.x = fmaxf(o.x, 0.f); o.y = fmaxf(o.y, 0.f);
            o.z = fmaxf(o.z, 0.f); o.w = fmaxf(o.w, 0.f);

            float s1 = o.x + o.y + o.z + o.w;
            float s2 = o.x * o.x + o.y * o.y + o.z * o.z + o.w * o.w;
            #pragma unroll
            for (int off = 16; off > 0; off >>= 1) {
                s1 += __shfl_xor_sync(0xffffffffu, s1, off);
                s2 += __shfl_xor_sync(0xffffffffu, s2, off);
            }
            float mu  = s1 * (1.f / 128.f);
            float var = s2 * (1.f / 128.f) - mu * mu;
            float rs  = rsqrtf(var + LN_EPS);

            float4 o4;
            o4.x = (o.x - mu) * rs * gs[c + 0] + lbs[c + 0];
            o4.y = (o.y - mu) * rs * gs[c + 1] + lbs[c + 1];
            o4.z = (o.z - mu) * rs * gs[c + 2] + lbs[c + 2];
            o4.w = (o.w - mu) * rs * gs[c + 3] + lbs[c + 3];
            ((float4*)(hout + (size_t)(v0 + r) * DM))[lane] = o4;
        }
    }
}

// ---------------- host launch ------------------------------------------------------
extern "C" void kernel_launch(void* const* d_in, const int* in_sizes, int n_in,
                              void* d_out, int out_size)
{
    const float* x      = (const float*)d_in[0];
    const int*   label  = (const int*)d_in[1];
    const int*   eidx   = (const int*)d_in[2];
    const int*   erel   = (const int*)d_in[3];
    const float* lemb   = (const float*)d_in[4];
    const float* Win    = (const float*)d_in[5];
    const float* bin    = (const float*)d_in[6];
    const float* relemb = (const float*)d_in[7];
    const float* Wn     = (const float*)d_in[8];
    const float* Wself  = (const float*)d_in[9];
    const float* bself  = (const float*)d_in[10];
    const float* Wr     = (const float*)d_in[11];
    const float* lng    = (const float*)d_in[12];
    const float* lnb    = (const float*)d_in[13];
    float* out = (float*)d_out;

    float *p_h, *p_h2;
    int *p_deg;
    cudaGetSymbolAddress((void**)&p_h,   g_h);
    cudaGetSymbolAddress((void**)&p_h2,  g_h2);
    cudaGetSymbolAddress((void**)&p_deg, g_deg);

    const int smemI = (KIN * DM + DM + 8 * 4 * KIN) * sizeof(float);
    const int smemN = (2 * DM * DM + RD * DM + 3 * DM + 8 * 4 * 288) * sizeof(float);
    cudaFuncSetAttribute(k_input, cudaFuncAttributeMaxDynamicSharedMemorySize, smemI);
    cudaFuncSetAttribute(k_node,  cudaFuncAttributeMaxDynamicSharedMemorySize, smemN);

    // CSR build
    k_zero_int<<<(NN + 255) / 256, 256>>>(p_deg, NN);
    k_deg<<<(EE + 255) / 256, 256>>>(eidx + EE);
    k_scan<<<1, 1024>>>();
    k_scatter<<<(EE + 255) / 256, 256>>>(eidx, eidx + EE, erel);

    // input projection
    k_input<<<148, 256, smemI>>>(x, label, lemb, Win, bin, p_h);

    const float* hin = p_h;
    for (int l = 0; l < 2; l++) {
        float* hout = (l == 0) ? p_h2 : out;
        k_gather<<<(NN + 7) / 8, 256>>>(hin, relemb + l * 1024 * RD);
        k_node<<<148, 256, smemN>>>(hin,
                                    Wself + l * DM * DM, Wn + l * DM * DM,
                                    Wr + l * RD * DM, bself + l * DM,
                                    lng + l * DM, lnb + l * DM, hout);
        hin = hout;
    }
}

// round 6
// speedup vs baseline: 1.2860x; 1.0373x over previous
#include <cuda_runtime.h>

#define NN 50000
#define EE 800000
#define DM 128
#define RD 32
#define KIN 160
#define LN_EPS 1e-5f

// ---------------- scratch ----------------------------------------------------
__device__ float g_h[NN * DM];
__device__ float g_h2[NN * DM];
__device__ float g_aggH[NN * DM];
__device__ float g_aggR[NN * RD];
__device__ float g_inv[NN];
__device__ int   g_deg[NN];
__device__ int   g_off[NN + 1];
__device__ int   g_cur[NN];
__device__ int2  g_csr[EE];        // (src, rel) grouped by dst

// ---------------- CSR build ----------------------------------------------------
__global__ void k_zero_int(int* __restrict__ p, int n) {
    int i = blockIdx.x * blockDim.x + threadIdx.x;
    if (i < n) p[i] = 0;
}

__global__ void k_deg(const int* __restrict__ dst) {
    int i = blockIdx.x * blockDim.x + threadIdx.x;
    if (i < EE) atomicAdd(&g_deg[dst[i]], 1);
}

__global__ __launch_bounds__(1024) void k_scan() {
    __shared__ int warp_sums[32];
    const int CH = (NN + 1023) / 1024;
    int t = threadIdx.x, lane = t & 31, w = t >> 5;
    int base = t * CH;
    int s = 0;
    for (int i = 0; i < CH; i++) {
        int idx = base + i;
        if (idx < NN) s += g_deg[idx];
    }
    int v = s;
    #pragma unroll
    for (int o = 1; o < 32; o <<= 1) {
        int u = __shfl_up_sync(0xffffffffu, v, o);
        if (lane >= o) v += u;
    }
    if (lane == 31) warp_sums[w] = v;
    __syncthreads();
    if (w == 0) {
        int u = warp_sums[lane];
        #pragma unroll
        for (int o = 1; o < 32; o <<= 1) {
            int uu = __shfl_up_sync(0xffffffffu, u, o);
            if (lane >= o) u += uu;
        }
        warp_sums[lane] = u;
    }
    __syncthreads();
    int excl = v - s + (w > 0 ? warp_sums[w - 1] : 0);
    int run = excl;
    for (int i = 0; i < CH; i++) {
        int idx = base + i;
        if (idx < NN) {
            int d = g_deg[idx];
            g_off[idx] = run;
            g_cur[idx] = run;
            g_inv[idx] = d > 0 ? (1.f / (float)d) : 0.f;
            run += d;
        }
    }
    if (t == 0) g_off[NN] = EE;
}

__global__ void k_scatter(const int* __restrict__ src, const int* __restrict__ dst,
                          const int* __restrict__ erel) {
    int i = blockIdx.x * blockDim.x + threadIdx.x;
    if (i < EE) {
        int d = dst[i];
        int pos = atomicAdd(&g_cur[d], 1);
        g_csr[pos] = make_int2(src[i], erel[i]);
    }
}

// ---------------- gather: aggH[v]=mean h[src], aggR[v]=mean rel[erel] ----------
__global__ __launch_bounds__(256) void k_gather(
    const float* __restrict__ hin, const float* __restrict__ rel)
{
    __shared__ int2 stage[8][32];
    int w = threadIdx.x >> 5, lane = threadIdx.x & 31;
    int v = blockIdx.x * 8 + w;
    if (v >= NN) return;
    int2* st = stage[w];

    int e = g_off[v], end = g_off[v + 1];
    float4 a0 = make_float4(0.f, 0.f, 0.f, 0.f), a1 = a0, a2 = a0, a3 = a0;
    float r0s = 0.f, r1s = 0.f, r2s = 0.f, r3s = 0.f;

    while (e < end) {
        int n = min(32, end - e);
        if (lane < n) st[lane] = g_csr[e + lane];
        __syncwarp();
        int j = 0;
        for (; j + 4 <= n; j += 4) {
            int2 p0 = st[j], p1 = st[j + 1], p2 = st[j + 2], p3 = st[j + 3];
            float4 h0 = ((const float4*)(hin + (size_t)p0.x * DM))[lane];
            float4 h1 = ((const float4*)(hin + (size_t)p1.x * DM))[lane];
            float4 h2 = ((const float4*)(hin + (size_t)p2.x * DM))[lane];
            float4 h3 = ((const float4*)(hin + (size_t)p3.x * DM))[lane];
            float q0 = rel[p0.y * RD + lane];
            float q1 = rel[p1.y * RD + lane];
            float q2 = rel[p2.y * RD + lane];
            float q3 = rel[p3.y * RD + lane];
            a0.x += h0.x; a0.y += h0.y; a0.z += h0.z; a0.w += h0.w;
            a1.x += h1.x; a1.y += h1.y; a1.z += h1.z; a1.w += h1.w;
            a2.x += h2.x; a2.y += h2.y; a2.z += h2.z; a2.w += h2.w;
            a3.x += h3.x; a3.y += h3.y; a3.z += h3.z; a3.w += h3.w;
            r0s += q0; r1s += q1; r2s += q2; r3s += q3;
        }
        for (; j < n; j++) {
            int2 p0 = st[j];
            float4 h0 = ((const float4*)(hin + (size_t)p0.x * DM))[lane];
            a0.x += h0.x; a0.y += h0.y; a0.z += h0.z; a0.w += h0.w;
            r0s += rel[p0.y * RD + lane];
        }
        e += n;
        __syncwarp();
    }

    float iv = g_inv[v];
    float4 acc;
    acc.x = (a0.x + a1.x + a2.x + a3.x) * iv;
    acc.y = (a0.y + a1.y + a2.y + a3.y) * iv;
    acc.z = (a0.z + a1.z + a2.z + a3.z) * iv;
    acc.w = (a0.w + a1.w + a2.w + a3.w) * iv;
    ((float4*)(g_aggH + (size_t)v * DM))[lane] = acc;
    g_aggR[v * RD + lane] = (r0s + r1s + r2s + r3s) * iv;
}

// ---------------- packed fp32 GEMM machinery -----------------------------------
extern __shared__ float smdyn[];

#define PFMA(D, A, B) \
    asm("fma.rn.f32x2 %0, %1, %2, %0;" : "+l"(D) : "l"(A), "l"(B));

__device__ __forceinline__ float phsum(unsigned long long v) {
    float lo = __uint_as_float((unsigned)v);
    float hi = __uint_as_float((unsigned)(v >> 32));
    return lo + hi;
}

// Conflict-free k-pair weight staging (same as R5): per k-pair kp a 2*DM region;
// A half (cols%4 in {0,1}) densely 16B/lane, B half (cols%4 in {2,3}) at +DM.
#define STAGE_PAIRS(Wp, W, K)                                              \
    for (int idx = tid; idx < ((K) / 2) * DM; idx += 256) {                \
        int kp  = idx / DM;                                                \
        int col = idx % DM;                                                \
        float w0 = (W)[(2 * kp) * DM + col];                               \
        float w1 = (W)[(2 * kp + 1) * DM + col];                           \
        int dst = kp * 2 * DM + ((col & 2) ? DM : 0)                       \
                + ((col >> 2) << 2) + ((col & 1) << 1);                    \
        (Wp)[dst] = w0; (Wp)[dst + 1] = w1;                                \
    }

// one input pair-vector (bi.x = k0k1, bi.y = k2k3) into 4 col-accumulators
#define PROWS(BI, R0, R1, R2, R3)                                                    \
    PFMA(R0, (BI).x, wA0.x) PFMA(R1, (BI).x, wA0.y) PFMA(R2, (BI).x, wB0.x) PFMA(R3, (BI).x, wB0.y) \
    PFMA(R0, (BI).y, wA1.x) PFMA(R1, (BI).y, wA1.y) PFMA(R2, (BI).y, wB1.x) PFMA(R3, (BI).y, wB1.y)

// 8-row GEMM segment; input base `in`, row stride STR
#define SEG8(Wb, OFF, LEN, STR)                                              \
    _Pragma("unroll 4")                                                      \
    for (int k = 0; k < (LEN); k += 4) {                                     \
        ulonglong2 b0 = *(const ulonglong2*)(in + 0 * (STR) + (OFF) + k);    \
        ulonglong2 b1 = *(const ulonglong2*)(in + 1 * (STR) + (OFF) + k);    \
        ulonglong2 b2 = *(const ulonglong2*)(in + 2 * (STR) + (OFF) + k);    \
        ulonglong2 b3 = *(const ulonglong2*)(in + 3 * (STR) + (OFF) + k);    \
        ulonglong2 b4 = *(const ulonglong2*)(in + 4 * (STR) + (OFF) + k);    \
        ulonglong2 b5 = *(const ulonglong2*)(in + 5 * (STR) + (OFF) + k);    \
        ulonglong2 b6 = *(const ulonglong2*)(in + 6 * (STR) + (OFF) + k);    \
        ulonglong2 b7 = *(const ulonglong2*)(in + 7 * (STR) + (OFF) + k);    \
        const float* wb = (Wb) + k * DM + c;                                 \
        ulonglong2 wA0 = *(const ulonglong2*)(wb);                           \
        ulonglong2 wB0 = *(const ulonglong2*)(wb + DM);                      \
        ulonglong2 wA1 = *(const ulonglong2*)(wb + 2 * DM);                  \
        ulonglong2 wB1 = *(const ulonglong2*)(wb + 3 * DM);                  \
        PROWS(b0, A00, A01, A02, A03)                                        \
        PROWS(b1, A10, A11, A12, A13)                                        \
        PROWS(b2, A20, A21, A22, A23)                                        \
        PROWS(b3, A30, A31, A32, A33)                                        \
        PROWS(b4, A40, A41, A42, A43)                                        \
        PROWS(b5, A50, A51, A52, A53)                                        \
        PROWS(b6, A60, A61, A62, A63)                                        \
        PROWS(b7, A70, A71, A72, A73)                                        \
    }

#define DECL_ACC8                                                   \
    unsigned long long A00 = 0, A01 = 0, A02 = 0, A03 = 0,          \
                       A10 = 0, A11 = 0, A12 = 0, A13 = 0,          \
                       A20 = 0, A21 = 0, A22 = 0, A23 = 0,          \
                       A30 = 0, A31 = 0, A32 = 0, A33 = 0,          \
                       A40 = 0, A41 = 0, A42 = 0, A43 = 0,          \
                       A50 = 0, A51 = 0, A52 = 0, A53 = 0,          \
                       A60 = 0, A61 = 0, A62 = 0, A63 = 0,          \
                       A70 = 0, A71 = 0, A72 = 0, A73 = 0;

#define ROWACC(R0, R1, R2, R3) \
    make_float4(phsum(R0) + bb.x, phsum(R1) + bb.y, phsum(R2) + bb.z, phsum(R3) + bb.w)

// ---------------- input projection ----------------------------------------------
__global__ __launch_bounds__(256) void k_input(
    const float* __restrict__ x, const int* __restrict__ label,
    const float* __restrict__ lemb, const float* __restrict__ W,
    const float* __restrict__ b, float* __restrict__ hout)
{
    float* Ws  = smdyn;             // KIN*DM (pair layout)
    float* bs  = Ws + KIN * DM;
    float* ins = bs + DM;           // 8 warps * 8 rows * KIN
    int tid = threadIdx.x;

    STAGE_PAIRS(Ws, W, KIN)
    for (int i = tid; i < DM; i += 256) bs[i] = b[i];
    __syncthreads();

    int w = tid >> 5, lane = tid & 31;
    int c = lane * 4;
    const int ntiles = NN / 8;   // 6250

    for (int tile = blockIdx.x * 8 + w; tile < ntiles; tile += gridDim.x * 8) {
        int v0 = tile * 8;
        float* in = ins + w * (8 * KIN);
        #pragma unroll
        for (int r = 0; r < 8; r++) {
            int v = v0 + r;
            float* inr = in + r * KIN;
            ((float4*)inr)[lane] = ((const float4*)(x + (size_t)v * DM))[lane];
            int lb = __ldg(&label[v]);
            inr[DM + lane] = lemb[lb * RD + lane];
        }
        __syncwarp();

        DECL_ACC8
        SEG8(Ws, 0, KIN, KIN)

        float4 bb = *(float4*)(bs + c);
        float4 accs[8];
        accs[0] = ROWACC(A00, A01, A02, A03);
        accs[1] = ROWACC(A10, A11, A12, A13);
        accs[2] = ROWACC(A20, A21, A22, A23);
        accs[3] = ROWACC(A30, A31, A32, A33);
        accs[4] = ROWACC(A40, A41, A42, A43);
        accs[5] = ROWACC(A50, A51, A52, A53);
        accs[6] = ROWACC(A60, A61, A62, A63);
        accs[7] = ROWACC(A70, A71, A72, A73);
        #pragma unroll
        for (int r = 0; r < 8; r++) {
            float4 o = accs[r];
            o.x = fmaxf(o.x, 0.f); o.y = fmaxf(o.y, 0.f);
            o.z = fmaxf(o.z, 0.f); o.w = fmaxf(o.w, 0.f);
            ((float4*)(hout + (size_t)(v0 + r) * DM))[lane] = o;
        }
    }
}

// ---------------- node pass: 3-GEMM + bias + relu + layernorm --------------------
__global__ __launch_bounds__(256) void k_node(
    const float* __restrict__ hin,
    const float* __restrict__ Wself, const float* __restrict__ Wn,
    const float* __restrict__ Wr, const float* __restrict__ bias,
    const float* __restrict__ lng, const float* __restrict__ lnb,
    float* __restrict__ hout)
{
    float* Ws  = smdyn;                 // DM*DM pair layout
    float* Wns = Ws + DM * DM;
    float* Wrs = Wns + DM * DM;         // RD*DM
    float* bs  = Wrs + RD * DM;
    float* gs  = bs + DM;
    float* lbs = gs + DM;
    float* ins = lbs + DM;              // 8 warps * 8 rows * 288

    int tid = threadIdx.x;
    STAGE_PAIRS(Ws,  Wself, DM)
    STAGE_PAIRS(Wns, Wn,    DM)
    STAGE_PAIRS(Wrs, Wr,    RD)
    for (int i = tid; i < DM; i += 256) {
        bs[i] = bias[i]; gs[i] = lng[i]; lbs[i] = lnb[i];
    }
    __syncthreads();

    int w = tid >> 5, lane = tid & 31;
    int c = lane * 4;
    const int ntiles = NN / 8;

    for (int tile = blockIdx.x * 8 + w; tile < ntiles; tile += gridDim.x * 8) {
        int v0 = tile * 8;
        float* in = ins + w * (8 * 288);
        #pragma unroll
        for (int r = 0; r < 8; r++) {
            int v = v0 + r;
            float* inr = in + r * 288;
            ((float4*)inr)[lane]        = ((const float4*)(hin + (size_t)v * DM))[lane];
            ((float4*)(inr + DM))[lane] = ((const float4*)(g_aggH + (size_t)v * DM))[lane];
            inr[2 * DM + lane]          = g_aggR[v * RD + lane];
        }
        __syncwarp();

        DECL_ACC8
        SEG8(Ws,  0,      DM, 288)
        SEG8(Wns, DM,     DM, 288)
        SEG8(Wrs, 2 * DM, RD, 288)

        float4 bb = *(float4*)(bs + c);
        float4 accs[8];
        accs[0] = ROWACC(A00, A01, A02, A03);
        accs[1] = ROWACC(A10, A11, A12, A13);
        accs[2] = ROWACC(A20, A21, A22, A23);
        accs[3] = ROWACC(A30, A31, A32, A33);
        accs[4] = ROWACC(A40, A41, A42, A43);
        accs[5] = ROWACC(A50, A51, A52, A53);
        accs[6] = ROWACC(A60, A61, A62, A63);
        accs[7] = ROWACC(A70, A71, A72, A73);

        #pragma unroll
        for (int r = 0; r < 8; r++) {
            float4 o = accs[r];
            o.x = fmaxf(o.x, 0.f); o.y = fmaxf(o.y, 0.f);
            o.z = fmaxf(o.z, 0.f); o.w = fmaxf(o.w, 0.f);

            float s1 = o.x + o.y + o.z + o.w;
            float s2 = o.x * o.x + o.y * o.y + o.z * o.z + o.w * o.w;
            #pragma unroll
            for (int off = 16; off > 0; off >>= 1) {
                s1 += __shfl_xor_sync(0xffffffffu, s1, off);
                s2 += __shfl_xor_sync(0xffffffffu, s2, off);
            }
            float mu  = s1 * (1.f / 128.f);
            float var = s2 * (1.f / 128.f) - mu * mu;
            float rs  = rsqrtf(var + LN_EPS);

            float4 o4;
            o4.x = (o.x - mu) * rs * gs[c + 0] + lbs[c + 0];
            o4.y = (o.y - mu) * rs * gs[c + 1] + lbs[c + 1];
            o4.z = (o.z - mu) * rs * gs[c + 2] + lbs[c + 2];
            o4.w = (o.w - mu) * rs * gs[c + 3] + lbs[c + 3];
            ((float4*)(hout + (size_t)(v0 + r) * DM))[lane] = o4;
        }
    }
}

// ---------------- host launch ------------------------------------------------------
extern "C" void kernel_launch(void* const* d_in, const int* in_sizes, int n_in,
                              void* d_out, int out_size)
{
    const float* x      = (const float*)d_in[0];
    const int*   label  = (const int*)d_in[1];
    const int*   eidx   = (const int*)d_in[2];
    const int*   erel   = (const int*)d_in[3];
    const float* lemb   = (const float*)d_in[4];
    const float* Win    = (const float*)d_in[5];
    const float* bin    = (const float*)d_in[6];
    const float* relemb = (const float*)d_in[7];
    const float* Wn     = (const float*)d_in[8];
    const float* Wself  = (const float*)d_in[9];
    const float* bself  = (const float*)d_in[10];
    const float* Wr     = (const float*)d_in[11];
    const float* lng    = (const float*)d_in[12];
    const float* lnb    = (const float*)d_in[13];
    float* out = (float*)d_out;

    float *p_h, *p_h2;
    int *p_deg;
    cudaGetSymbolAddress((void**)&p_h,   g_h);
    cudaGetSymbolAddress((void**)&p_h2,  g_h2);
    cudaGetSymbolAddress((void**)&p_deg, g_deg);

    const int smemI = (KIN * DM + DM + 8 * 8 * KIN) * sizeof(float);                   // ~121 KB
    const int smemN = (2 * DM * DM + RD * DM + 3 * DM + 8 * 8 * 288) * sizeof(float);  // ~218 KB
    cudaFuncSetAttribute(k_input, cudaFuncAttributeMaxDynamicSharedMemorySize, smemI);
    cudaFuncSetAttribute(k_node,  cudaFuncAttributeMaxDynamicSharedMemorySize, smemN);

    // CSR build
    k_zero_int<<<(NN + 255) / 256, 256>>>(p_deg, NN);
    k_deg<<<(EE + 255) / 256, 256>>>(eidx + EE);
    k_scan<<<1, 1024>>>();
    k_scatter<<<(EE + 255) / 256, 256>>>(eidx, eidx + EE, erel);

    // input projection
    k_input<<<148, 256, smemI>>>(x, label, lemb, Win, bin, p_h);

    const float* hin = p_h;
    for (int l = 0; l < 2; l++) {
        float* hout = (l == 0) ? p_h2 : out;
        k_gather<<<(NN + 7) / 8, 256>>>(hin, relemb + l * 1024 * RD);
        k_node<<<148, 256, smemN>>>(hin,
                                    Wself + l * DM * DM, Wn + l * DM * DM,
                                    Wr + l * RD * DM, bself + l * DM,
                                    lng + l * DM, lnb + l * DM, hout);
        hin = hout;
    }
}